// round 1
// baseline (speedup 1.0000x reference)
#include <cuda_runtime.h>

// ---------------------------------------------------------------------------
// LowrankLearnableHash: 3x bilinear plane samples (12ch, 256^2) -> triple
// product -> rank-4 sum -> 3D coords -> trilinear sample of 32ch 64^3 volume.
//
// Strategy:
//   prep_planes: [12,256,256] -> [256,256,16] (channel-last, padded to 16 so
//                each corner is three aligned float4 loads within one 64B row)
//   prep_feat:   [32,64,64,64] -> [64,64,64,32] (channel-last: each trilinear
//                corner is one contiguous 128B line -> 8 float4 loads)
//   lrh_main:    thread-per-point fused kernel, float4 gathers, float4 stores.
// ---------------------------------------------------------------------------

namespace {
constexpr int RESO  = 256;
constexpr int CPAD  = 16;     // 12 channels padded to 16 floats (64 B rows)
constexpr int FR    = 64;     // feature resolution
constexpr int FD    = 32;     // feature channels
constexpr int PLANE_ELEMS = RESO * RESO * CPAD;
constexpr int NVOX = FR * FR * FR;
}

__device__ float g_planes[3][PLANE_ELEMS];        // 12 MB
__device__ float g_feat[NVOX * FD];               // 32 MB

// ---------------------------------------------------------------------------
// Prep: planes -> channel-last padded
// ---------------------------------------------------------------------------
__global__ void prep_planes(const float* __restrict__ p0,
                            const float* __restrict__ p1,
                            const float* __restrict__ p2) {
    int t = blockIdx.x * blockDim.x + threadIdx.x;   // texel id
    if (t >= RESO * RESO) return;
    int p = blockIdx.y;
    const float* src = (p == 0) ? p0 : ((p == 1) ? p1 : p2);

    float v[16];
#pragma unroll
    for (int c = 0; c < 12; ++c) v[c] = src[c * (RESO * RESO) + t];
    v[12] = v[13] = v[14] = v[15] = 0.0f;

    float4* dst = reinterpret_cast<float4*>(&g_planes[p][t * CPAD]);
    dst[0] = make_float4(v[0],  v[1],  v[2],  v[3]);
    dst[1] = make_float4(v[4],  v[5],  v[6],  v[7]);
    dst[2] = make_float4(v[8],  v[9],  v[10], v[11]);
    dst[3] = make_float4(v[12], v[13], v[14], v[15]);
}

// ---------------------------------------------------------------------------
// Prep: features -> channel-last
// ---------------------------------------------------------------------------
__global__ void prep_feat(const float* __restrict__ f) {
    int v = blockIdx.x * blockDim.x + threadIdx.x;   // voxel id
    if (v >= NVOX) return;
    float tmp[FD];
#pragma unroll
    for (int c = 0; c < FD; ++c) tmp[c] = f[c * NVOX + v];
    float4* dst = reinterpret_cast<float4*>(&g_feat[(size_t)v * FD]);
#pragma unroll
    for (int j = 0; j < FD / 4; ++j)
        dst[j] = make_float4(tmp[4 * j], tmp[4 * j + 1], tmp[4 * j + 2], tmp[4 * j + 3]);
}

// ---------------------------------------------------------------------------
// Bilinear plane sample (12 channels as 3x float4), align_corners + clamp,
// matching the reference: x0 = clamp(floor(x), 0, W-2), wx = x - x0.
// ---------------------------------------------------------------------------
__device__ __forceinline__ void sample_plane(const float* __restrict__ pl,
                                             float a, float b, float4 res[3]) {
    float x = fminf(fmaxf((a + 1.0f) * (0.5f * (RESO - 1)), 0.0f), (float)(RESO - 1));
    float y = fminf(fmaxf((b + 1.0f) * (0.5f * (RESO - 1)), 0.0f), (float)(RESO - 1));
    int x0 = min((int)x, RESO - 2);
    int y0 = min((int)y, RESO - 2);
    float fx = x - (float)x0;
    float fy = y - (float)y0;

    const float4* base = reinterpret_cast<const float4*>(pl)
                       + (y0 * RESO + x0) * (CPAD / 4);
    constexpr int DX = CPAD / 4;          // +1 texel in x (in float4 units)
    constexpr int DY = RESO * (CPAD / 4); // +1 texel in y

    float w00 = (1.0f - fx) * (1.0f - fy);
    float w01 = fx * (1.0f - fy);
    float w10 = (1.0f - fx) * fy;
    float w11 = fx * fy;

#pragma unroll
    for (int c = 0; c < 3; ++c) {
        float4 v00 = __ldg(base + c);
        float4 v01 = __ldg(base + DX + c);
        float4 v10 = __ldg(base + DY + c);
        float4 v11 = __ldg(base + DY + DX + c);
        float4 r;
        r.x = fmaf(v00.x, w00, fmaf(v01.x, w01, fmaf(v10.x, w10, v11.x * w11)));
        r.y = fmaf(v00.y, w00, fmaf(v01.y, w01, fmaf(v10.y, w10, v11.y * w11)));
        r.z = fmaf(v00.z, w00, fmaf(v01.z, w01, fmaf(v10.z, w10, v11.z * w11)));
        r.w = fmaf(v00.w, w00, fmaf(v01.w, w01, fmaf(v10.w, w10, v11.w * w11)));
        res[c] = r;
    }
}

// ---------------------------------------------------------------------------
// Main fused kernel: thread per point.
// ---------------------------------------------------------------------------
__global__ void lrh_main(const float* __restrict__ pts,
                         float* __restrict__ out, int n) {
    int i = blockIdx.x * blockDim.x + threadIdx.x;
    if (i >= n) return;

    float px = __ldg(pts + 3 * i);
    float py = __ldg(pts + 3 * i + 1);
    float pz = __ldg(pts + 3 * i + 2);

    float4 s01[3], s02[3], s12[3];
    sample_plane(g_planes[0], px, py, s01);
    sample_plane(g_planes[1], px, pz, s02);
    sample_plane(g_planes[2], py, pz, s12);

    // channel c = d*4 + r  ->  chunk d holds the 4 ranks of coord d
    float coords[3];
#pragma unroll
    for (int c = 0; c < 3; ++c) {
        float4 a = s01[c], b = s02[c], d = s12[c];
        coords[c] = a.x * b.x * d.x + a.y * b.y * d.y
                  + a.z * b.z * d.z + a.w * b.w * d.w;
    }

    // Trilinear sample of channel-last features.
    float x = fminf(fmaxf((coords[0] + 1.0f) * (0.5f * (FR - 1)), 0.0f), (float)(FR - 1));
    float y = fminf(fmaxf((coords[1] + 1.0f) * (0.5f * (FR - 1)), 0.0f), (float)(FR - 1));
    float z = fminf(fmaxf((coords[2] + 1.0f) * (0.5f * (FR - 1)), 0.0f), (float)(FR - 1));
    int x0 = min((int)x, FR - 2);
    int y0 = min((int)y, FR - 2);
    int z0 = min((int)z, FR - 2);
    float fx = x - (float)x0;
    float fy = y - (float)y0;
    float fz = z - (float)z0;

    const float4* fb = reinterpret_cast<const float4*>(g_feat)
                     + ((size_t)(z0 * FR + y0) * FR + x0) * (FD / 4);
    constexpr int SX = FD / 4;            // +1 voxel in x (float4 units)
    constexpr int SY = FR * FD / 4;       // +1 voxel in y
    constexpr int SZ = FR * FR * FD / 4;  // +1 voxel in z

    float wx[2] = {1.0f - fx, fx};
    float wy[2] = {1.0f - fy, fy};
    float wz[2] = {1.0f - fz, fz};

    float4 acc[8];
#pragma unroll
    for (int j = 0; j < 8; ++j) acc[j] = make_float4(0.f, 0.f, 0.f, 0.f);

#pragma unroll
    for (int dz = 0; dz < 2; ++dz) {
#pragma unroll
        for (int dy = 0; dy < 2; ++dy) {
#pragma unroll
            for (int dx = 0; dx < 2; ++dx) {
                float w = wz[dz] * wy[dy] * wx[dx];
                const float4* cp = fb + dz * SZ + dy * SY + dx * SX;
#pragma unroll
                for (int j = 0; j < 8; ++j) {
                    float4 v = __ldg(cp + j);
                    acc[j].x = fmaf(w, v.x, acc[j].x);
                    acc[j].y = fmaf(w, v.y, acc[j].y);
                    acc[j].z = fmaf(w, v.z, acc[j].z);
                    acc[j].w = fmaf(w, v.w, acc[j].w);
                }
            }
        }
    }

    float4* op = reinterpret_cast<float4*>(out) + (size_t)i * 8;
#pragma unroll
    for (int j = 0; j < 8; ++j) op[j] = acc[j];
}

// ---------------------------------------------------------------------------
extern "C" void kernel_launch(void* const* d_in, const int* in_sizes, int n_in,
                              void* d_out, int out_size) {
    const float* pts  = (const float*)d_in[0];
    const float* p01  = (const float*)d_in[1];
    const float* p02  = (const float*)d_in[2];
    const float* p12  = (const float*)d_in[3];
    const float* feat = (const float*)d_in[4];
    float* out = (float*)d_out;
    int n = in_sizes[0] / 3;

    prep_planes<<<dim3((RESO * RESO + 255) / 256, 3), 256>>>(p01, p02, p12);
    prep_feat<<<(NVOX + 255) / 256, 256>>>(feat);
    lrh_main<<<(n + 255) / 256, 256>>>(pts, out, n);
}

// round 2
// speedup vs baseline: 2.1242x; 2.1242x over previous
#include <cuda_runtime.h>
#include <cuda_fp16.h>

// ---------------------------------------------------------------------------
// LowrankLearnableHash, round 2: quad-cooperative gathers + fp16 planes.
//
//   prep_planes: [12,256,256] fp32 -> [256,256,16] fp16 (32B/texel, ch 12..15=0)
//   prep_feat:   [32,64,64,64] -> [64,64,64,32] fp32 channel-last
//   lrh_main:    4 lanes per point. Lane j owns channels 4j..4j+3 (= the 4
//                ranks of output dim j), so each plane-corner fetch is an 8B
//                load and the quad's 4 lanes cover one 32B texel row ->
//                per warp-LDG only ~8 distinct cache lines (vs 32 before).
//                coord_j computed in lane j, shared via quad shuffles.
// ---------------------------------------------------------------------------

namespace {
constexpr int RESO = 256;
constexpr int HPAD = 16;      // 16 fp16 = 32 B per texel
constexpr int FR   = 64;
constexpr int FD   = 32;
constexpr int NVOX = FR * FR * FR;
}

__device__ __align__(256) __half g_planes_h[3][RESO * RESO * HPAD];  // 6 MB
__device__ __align__(256) float  g_feat[NVOX * FD];                  // 32 MB

// ---------------------------------------------------------------------------
__global__ void prep_planes(const float* __restrict__ p0,
                            const float* __restrict__ p1,
                            const float* __restrict__ p2) {
    int t = blockIdx.x * blockDim.x + threadIdx.x;
    if (t >= RESO * RESO) return;
    int p = blockIdx.y;
    const float* src = (p == 0) ? p0 : ((p == 1) ? p1 : p2);

    struct alignas(32) H16 { __half h[16]; } tmp;
#pragma unroll
    for (int c = 0; c < 12; ++c) tmp.h[c] = __float2half(src[c * (RESO * RESO) + t]);
#pragma unroll
    for (int c = 12; c < 16; ++c) tmp.h[c] = __float2half(0.0f);

    uint4* dst = reinterpret_cast<uint4*>(&g_planes_h[p][t * HPAD]);
    const uint4* s = reinterpret_cast<const uint4*>(&tmp);
    dst[0] = s[0];
    dst[1] = s[1];
}

// ---------------------------------------------------------------------------
__global__ void prep_feat(const float* __restrict__ f) {
    int v = blockIdx.x * blockDim.x + threadIdx.x;
    if (v >= NVOX) return;
    float tmp[FD];
#pragma unroll
    for (int c = 0; c < FD; ++c) tmp[c] = f[c * NVOX + v];
    float4* dst = reinterpret_cast<float4*>(&g_feat[(size_t)v * FD]);
#pragma unroll
    for (int j = 0; j < FD / 4; ++j)
        dst[j] = make_float4(tmp[4 * j], tmp[4 * j + 1], tmp[4 * j + 2], tmp[4 * j + 3]);
}

// ---------------------------------------------------------------------------
__device__ __forceinline__ void h4_to_f4(uint2 u, float f[4]) {
    __half2 h0 = *reinterpret_cast<__half2*>(&u.x);
    __half2 h1 = *reinterpret_cast<__half2*>(&u.y);
    float2 a = __half22float2(h0);
    float2 b = __half22float2(h1);
    f[0] = a.x; f[1] = a.y; f[2] = b.x; f[3] = b.y;
}

// Bilinear sample of one plane, lane-local 4-channel chunk j.
__device__ __forceinline__ void sample_plane_q(const __half* __restrict__ pl,
                                               float a, float b, int j,
                                               float r[4]) {
    float x = fminf(fmaxf((a + 1.0f) * (0.5f * (RESO - 1)), 0.0f), (float)(RESO - 1));
    float y = fminf(fmaxf((b + 1.0f) * (0.5f * (RESO - 1)), 0.0f), (float)(RESO - 1));
    int x0 = min((int)x, RESO - 2);
    int y0 = min((int)y, RESO - 2);
    float fx = x - (float)x0;
    float fy = y - (float)y0;

    const __half* base = pl + ((y0 * RESO + x0) * HPAD) + j * 4;
    constexpr int DX = HPAD;         // +1 texel in x (halfs)
    constexpr int DY = RESO * HPAD;  // +1 texel in y

    uint2 u00 = __ldg(reinterpret_cast<const uint2*>(base));
    uint2 u01 = __ldg(reinterpret_cast<const uint2*>(base + DX));
    uint2 u10 = __ldg(reinterpret_cast<const uint2*>(base + DY));
    uint2 u11 = __ldg(reinterpret_cast<const uint2*>(base + DY + DX));

    float v00[4], v01[4], v10[4], v11[4];
    h4_to_f4(u00, v00); h4_to_f4(u01, v01);
    h4_to_f4(u10, v10); h4_to_f4(u11, v11);

    float w00 = (1.0f - fx) * (1.0f - fy);
    float w01 = fx * (1.0f - fy);
    float w10 = (1.0f - fx) * fy;
    float w11 = fx * fy;

#pragma unroll
    for (int k = 0; k < 4; ++k)
        r[k] = fmaf(v00[k], w00, fmaf(v01[k], w01, fmaf(v10[k], w10, v11[k] * w11)));
}

// ---------------------------------------------------------------------------
// 4 lanes per point. Lane j in {0,1,2}: channel chunk j == output dim j.
// ---------------------------------------------------------------------------
__global__ void lrh_main(const float* __restrict__ pts,
                         float* __restrict__ out, int n) {
    int t = blockIdx.x * blockDim.x + threadIdx.x;
    int i = t >> 2;          // point id
    int j = t & 3;           // quad lane (channel chunk)
    if (i >= n) return;

    float px = __ldg(pts + 3 * i);
    float py = __ldg(pts + 3 * i + 1);
    float pz = __ldg(pts + 3 * i + 2);

    float s01[4], s02[4], s12[4];
    sample_plane_q(g_planes_h[0], px, py, j, s01);
    sample_plane_q(g_planes_h[1], px, pz, j, s02);
    sample_plane_q(g_planes_h[2], py, pz, j, s12);

    // coord of dim j (lane 3 computes 0 from padding; unused)
    float coord = s01[0] * s02[0] * s12[0]
                + s01[1] * s02[1] * s12[1]
                + s01[2] * s02[2] * s12[2]
                + s01[3] * s02[3] * s12[3];

    float cx = __shfl_sync(0xffffffffu, coord, 0, 4);
    float cy = __shfl_sync(0xffffffffu, coord, 1, 4);
    float cz = __shfl_sync(0xffffffffu, coord, 2, 4);

    // Trilinear sample, lane j covers channels 8j..8j+7.
    float x = fminf(fmaxf((cx + 1.0f) * (0.5f * (FR - 1)), 0.0f), (float)(FR - 1));
    float y = fminf(fmaxf((cy + 1.0f) * (0.5f * (FR - 1)), 0.0f), (float)(FR - 1));
    float z = fminf(fmaxf((cz + 1.0f) * (0.5f * (FR - 1)), 0.0f), (float)(FR - 1));
    int x0 = min((int)x, FR - 2);
    int y0 = min((int)y, FR - 2);
    int z0 = min((int)z, FR - 2);
    float fx = x - (float)x0;
    float fy = y - (float)y0;
    float fz = z - (float)z0;

    const float4* fb = reinterpret_cast<const float4*>(g_feat)
                     + ((size_t)(z0 * FR + y0) * FR + x0) * (FD / 4) + 2 * j;
    constexpr int SX = FD / 4;
    constexpr int SY = FR * FD / 4;
    constexpr int SZ = FR * FR * FD / 4;

    float wx[2] = {1.0f - fx, fx};
    float wy[2] = {1.0f - fy, fy};
    float wz[2] = {1.0f - fz, fz};

    float4 a0 = make_float4(0.f, 0.f, 0.f, 0.f);
    float4 a1 = make_float4(0.f, 0.f, 0.f, 0.f);

#pragma unroll
    for (int dz = 0; dz < 2; ++dz) {
#pragma unroll
        for (int dy = 0; dy < 2; ++dy) {
#pragma unroll
            for (int dx = 0; dx < 2; ++dx) {
                float w = wz[dz] * wy[dy] * wx[dx];
                const float4* cp = fb + dz * SZ + dy * SY + dx * SX;
                float4 v0 = __ldg(cp);
                float4 v1 = __ldg(cp + 1);
                a0.x = fmaf(w, v0.x, a0.x); a0.y = fmaf(w, v0.y, a0.y);
                a0.z = fmaf(w, v0.z, a0.z); a0.w = fmaf(w, v0.w, a0.w);
                a1.x = fmaf(w, v1.x, a1.x); a1.y = fmaf(w, v1.y, a1.y);
                a1.z = fmaf(w, v1.z, a1.z); a1.w = fmaf(w, v1.w, a1.w);
            }
        }
    }

    float4* op = reinterpret_cast<float4*>(out) + (size_t)i * (FD / 4) + 2 * j;
    op[0] = a0;
    op[1] = a1;
}

// ---------------------------------------------------------------------------
extern "C" void kernel_launch(void* const* d_in, const int* in_sizes, int n_in,
                              void* d_out, int out_size) {
    const float* pts  = (const float*)d_in[0];
    const float* p01  = (const float*)d_in[1];
    const float* p02  = (const float*)d_in[2];
    const float* p12  = (const float*)d_in[3];
    const float* feat = (const float*)d_in[4];
    float* out = (float*)d_out;
    int n = in_sizes[0] / 3;

    prep_planes<<<dim3((RESO * RESO + 255) / 256, 3), 256>>>(p01, p02, p12);
    prep_feat<<<(NVOX + 255) / 256, 256>>>(feat);

    int threads = 4 * n;
    lrh_main<<<(threads + 255) / 256, 256>>>(pts, out, n);
}

// round 3
// speedup vs baseline: 2.1964x; 1.0340x over previous
#include <cuda_runtime.h>
#include <cuda_fp16.h>

// ---------------------------------------------------------------------------
// LowrankLearnableHash, round 3: 2 lanes/point, fp16 planes + fp16 features,
// half2 math everywhere, fp32 only for coords/indices and final store.
//
//   g_planes_h: [3][256*256*16] fp16 channel-last, 32 B/texel (ch 12..15 = 0)
//   g_feat_h:   [64^3 * 32] fp16 channel-last, 64 B/voxel
//
//   lrh_main: pair lane j in {0,1} owns channels 16j..16j+15 of the output
//   and half-chunks of every gather. Plane corner = 1x LDG.128 per lane
//   (quad-pair covers the 32B texel row). Dims 0,1 reduce in lane 0,
//   dim 2 in lane 1; shared via width-2 shuffles.
// ---------------------------------------------------------------------------

namespace {
constexpr int RESO = 256;
constexpr int HPAD = 16;      // 16 fp16 = 32 B per texel
constexpr int FR   = 64;
constexpr int FD   = 32;
constexpr int NVOX = FR * FR * FR;
}

__device__ __align__(256) __half g_planes_h[3][RESO * RESO * HPAD];  // 6 MB
__device__ __align__(256) __half g_feat_h[NVOX * FD];                // 16 MB

// ---------------------------------------------------------------------------
__global__ void prep_planes(const float* __restrict__ p0,
                            const float* __restrict__ p1,
                            const float* __restrict__ p2) {
    int t = blockIdx.x * blockDim.x + threadIdx.x;
    if (t >= RESO * RESO) return;
    int p = blockIdx.y;
    const float* src = (p == 0) ? p0 : ((p == 1) ? p1 : p2);

    struct alignas(32) H16 { __half h[16]; } tmp;
#pragma unroll
    for (int c = 0; c < 12; ++c) tmp.h[c] = __float2half(src[c * (RESO * RESO) + t]);
#pragma unroll
    for (int c = 12; c < 16; ++c) tmp.h[c] = __float2half(0.0f);

    uint4* dst = reinterpret_cast<uint4*>(&g_planes_h[p][t * HPAD]);
    const uint4* s = reinterpret_cast<const uint4*>(&tmp);
    dst[0] = s[0];
    dst[1] = s[1];
}

// ---------------------------------------------------------------------------
__global__ void prep_feat(const float* __restrict__ f) {
    int v = blockIdx.x * blockDim.x + threadIdx.x;
    if (v >= NVOX) return;
    struct alignas(32) H32 { __half h[FD]; } tmp;
#pragma unroll
    for (int c = 0; c < FD; ++c) tmp.h[c] = __float2half(f[c * NVOX + v]);
    uint4* dst = reinterpret_cast<uint4*>(&g_feat_h[(size_t)v * FD]);
    const uint4* s = reinterpret_cast<const uint4*>(&tmp);
#pragma unroll
    for (int k = 0; k < 4; ++k) dst[k] = s[k];
}

// ---------------------------------------------------------------------------
// Bilinear plane sample in half2; lane j covers halfs [8j .. 8j+7] (4 half2).
// ---------------------------------------------------------------------------
__device__ __forceinline__ void sample_plane2(const __half* __restrict__ pl,
                                              float a, float b, int j,
                                              __half2 r[4]) {
    float x = fminf(fmaxf((a + 1.0f) * (0.5f * (RESO - 1)), 0.0f), (float)(RESO - 1));
    float y = fminf(fmaxf((b + 1.0f) * (0.5f * (RESO - 1)), 0.0f), (float)(RESO - 1));
    int x0 = min((int)x, RESO - 2);
    int y0 = min((int)y, RESO - 2);
    float fx = x - (float)x0;
    float fy = y - (float)y0;

    const uint4* base = reinterpret_cast<const uint4*>(pl + (y0 * RESO + x0) * HPAD) + j;
    constexpr int DX = 2;           // +1 texel in x, uint4 units (32 B)
    constexpr int DY = RESO * 2;    // +1 texel in y

    uint4 u00 = __ldg(base);
    uint4 u01 = __ldg(base + DX);
    uint4 u10 = __ldg(base + DY);
    uint4 u11 = __ldg(base + DY + DX);

    __half2 w00 = __float2half2_rn((1.0f - fx) * (1.0f - fy));
    __half2 w01 = __float2half2_rn(fx * (1.0f - fy));
    __half2 w10 = __float2half2_rn((1.0f - fx) * fy);
    __half2 w11 = __float2half2_rn(fx * fy);

    const __half2* v00 = reinterpret_cast<const __half2*>(&u00);
    const __half2* v01 = reinterpret_cast<const __half2*>(&u01);
    const __half2* v10 = reinterpret_cast<const __half2*>(&u10);
    const __half2* v11 = reinterpret_cast<const __half2*>(&u11);

#pragma unroll
    for (int k = 0; k < 4; ++k) {
        __half2 t = __hmul2(v00[k], w00);
        t = __hfma2(v01[k], w01, t);
        t = __hfma2(v10[k], w10, t);
        r[k] = __hfma2(v11[k], w11, t);
    }
}

// ---------------------------------------------------------------------------
// 2 lanes per point. Lane j owns channels 16j..16j+15 of the feature output
// and half-chunk j of the 12 plane channels (lane0: ch0-7 = dims 0,1;
// lane1: ch8-11 = dim 2, ch12-15 pad).
// ---------------------------------------------------------------------------
__global__ void lrh_main(const float* __restrict__ pts,
                         float* __restrict__ out, int n) {
    int t = blockIdx.x * blockDim.x + threadIdx.x;
    int i = t >> 1;
    int j = t & 1;
    if (i >= n) return;

    float px = __ldg(pts + 3 * i);
    float py = __ldg(pts + 3 * i + 1);
    float pz = __ldg(pts + 3 * i + 2);

    __half2 s01[4], s02[4], s12[4];
    sample_plane2(g_planes_h[0], px, py, j, s01);
    sample_plane2(g_planes_h[1], px, pz, j, s02);
    sample_plane2(g_planes_h[2], py, pz, j, s12);

    // triple product per channel pair
    __half2 h0 = __hmul2(__hmul2(s01[0], s02[0]), s12[0]);
    __half2 h1 = __hmul2(__hmul2(s01[1], s02[1]), s12[1]);
    __half2 h2 = __hmul2(__hmul2(s01[2], s02[2]), s12[2]);
    __half2 h3 = __hmul2(__hmul2(s01[3], s02[3]), s12[3]);

    // lane0: ca = coord0 (ch0-3), cb = coord1 (ch4-7)
    // lane1: ca = coord2 (ch8-11), cb = pad (0)
    float2 f0 = __half22float2(h0);
    float2 f1 = __half22float2(h1);
    float2 f2 = __half22float2(h2);
    float2 f3 = __half22float2(h3);
    float ca = (f0.x + f0.y) + (f1.x + f1.y);
    float cb = (f2.x + f2.y) + (f3.x + f3.y);

    float cx = __shfl_sync(0xffffffffu, ca, 0, 2);
    float cy = __shfl_sync(0xffffffffu, cb, 0, 2);
    float cz = __shfl_sync(0xffffffffu, ca, 1, 2);

    // Trilinear sample of fp16 channel-last features; lane j: ch 16j..16j+15.
    float x = fminf(fmaxf((cx + 1.0f) * (0.5f * (FR - 1)), 0.0f), (float)(FR - 1));
    float y = fminf(fmaxf((cy + 1.0f) * (0.5f * (FR - 1)), 0.0f), (float)(FR - 1));
    float z = fminf(fmaxf((cz + 1.0f) * (0.5f * (FR - 1)), 0.0f), (float)(FR - 1));
    int x0 = min((int)x, FR - 2);
    int y0 = min((int)y, FR - 2);
    int z0 = min((int)z, FR - 2);
    float fx = x - (float)x0;
    float fy = y - (float)y0;
    float fz = z - (float)z0;

    // uint4 = 8 halfs; voxel = 4 uint4; lane j takes 2 uint4 at offset 2j.
    const uint4* fb = reinterpret_cast<const uint4*>(g_feat_h)
                    + ((size_t)((z0 * FR + y0) * FR + x0)) * 4 + 2 * j;
    constexpr int SX = 4;
    constexpr int SY = FR * 4;
    constexpr int SZ = FR * FR * 4;

    float wx[2] = {1.0f - fx, fx};
    float wy[2] = {1.0f - fy, fy};
    float wz[2] = {1.0f - fz, fz};

    __half2 acc[8];
#pragma unroll
    for (int k = 0; k < 8; ++k) acc[k] = __float2half2_rn(0.0f);

#pragma unroll
    for (int dz = 0; dz < 2; ++dz) {
#pragma unroll
        for (int dy = 0; dy < 2; ++dy) {
#pragma unroll
            for (int dx = 0; dx < 2; ++dx) {
                __half2 w = __float2half2_rn(wz[dz] * wy[dy] * wx[dx]);
                const uint4* cp = fb + dz * SZ + dy * SY + dx * SX;
                uint4 ua = __ldg(cp);
                uint4 ub = __ldg(cp + 1);
                const __half2* va = reinterpret_cast<const __half2*>(&ua);
                const __half2* vb = reinterpret_cast<const __half2*>(&ub);
#pragma unroll
                for (int k = 0; k < 4; ++k) {
                    acc[k]     = __hfma2(va[k], w, acc[k]);
                    acc[k + 4] = __hfma2(vb[k], w, acc[k + 4]);
                }
            }
        }
    }

    // convert to fp32 and store 64 B (channels 16j..16j+15)
    float4 o[4];
#pragma unroll
    for (int k = 0; k < 4; ++k) {
        float2 a = __half22float2(acc[2 * k]);
        float2 b = __half22float2(acc[2 * k + 1]);
        o[k] = make_float4(a.x, a.y, b.x, b.y);
    }
    float4* op = reinterpret_cast<float4*>(out) + (size_t)i * (FD / 4) + 4 * j;
#pragma unroll
    for (int k = 0; k < 4; ++k) op[k] = o[k];
}

// ---------------------------------------------------------------------------
extern "C" void kernel_launch(void* const* d_in, const int* in_sizes, int n_in,
                              void* d_out, int out_size) {
    const float* pts  = (const float*)d_in[0];
    const float* p01  = (const float*)d_in[1];
    const float* p02  = (const float*)d_in[2];
    const float* p12  = (const float*)d_in[3];
    const float* feat = (const float*)d_in[4];
    float* out = (float*)d_out;
    int n = in_sizes[0] / 3;

    prep_planes<<<dim3((RESO * RESO + 255) / 256, 3), 256>>>(p01, p02, p12);
    prep_feat<<<(NVOX + 255) / 256, 256>>>(feat);

    int threads = 2 * n;
    lrh_main<<<(threads + 255) / 256, 256>>>(pts, out, n);
}

// round 4
// speedup vs baseline: 2.7807x; 1.2660x over previous
#include <cuda_runtime.h>
#include <cuda_fp16.h>

// ---------------------------------------------------------------------------
// LowrankLearnableHash, round 4: quad-cooperative ROW-PAIR gathers.
//
//   g_planes_h: [3][256*256*16] fp16 channel-last, 32 B/texel (ch 12..15 = 0)
//   g_feat_h:   [64^3 * 32]     fp16 channel-last, 64 B/voxel
//
//   lrh_main: 4 lanes per point. For each plane, ONE warp instruction loads a
//   contiguous 64 B row-pair (texels x0 and x0+1): lane k takes bytes
//   [16k,16k+16). Lanes 0,1 = texel x0 (ch 0-7 / 8-15), lanes 2,3 = texel
//   x0+1. y-blend in-lane, x-blend via shfl_xor(2). Per-warp-instruction
//   distinct lines drop from 16 to ~10, and corner instructions per point
//   from 12 to 6.
//   Feature trilinear: lane k owns channels 8k..8k+7, fp32 accumulation.
// ---------------------------------------------------------------------------

namespace {
constexpr int RESO = 256;
constexpr int HPAD = 16;      // 16 fp16 = 32 B per texel
constexpr int FR   = 64;
constexpr int FD   = 32;
constexpr int NVOX = FR * FR * FR;
}

__device__ __align__(256) __half g_planes_h[3][RESO * RESO * HPAD];  // 6 MB
__device__ __align__(256) __half g_feat_h[NVOX * FD];                // 16 MB

// ---------------------------------------------------------------------------
__global__ void prep_planes(const float* __restrict__ p0,
                            const float* __restrict__ p1,
                            const float* __restrict__ p2) {
    int t = blockIdx.x * blockDim.x + threadIdx.x;
    if (t >= RESO * RESO) return;
    int p = blockIdx.y;
    const float* src = (p == 0) ? p0 : ((p == 1) ? p1 : p2);

    struct alignas(32) H16 { __half h[16]; } tmp;
#pragma unroll
    for (int c = 0; c < 12; ++c) tmp.h[c] = __float2half(src[c * (RESO * RESO) + t]);
#pragma unroll
    for (int c = 12; c < 16; ++c) tmp.h[c] = __float2half(0.0f);

    uint4* dst = reinterpret_cast<uint4*>(&g_planes_h[p][t * HPAD]);
    const uint4* s = reinterpret_cast<const uint4*>(&tmp);
    dst[0] = s[0];
    dst[1] = s[1];
}

// ---------------------------------------------------------------------------
__global__ void prep_feat(const float* __restrict__ f) {
    int v = blockIdx.x * blockDim.x + threadIdx.x;
    if (v >= NVOX) return;
    struct alignas(32) H32 { __half h[FD]; } tmp;
#pragma unroll
    for (int c = 0; c < FD; ++c) tmp.h[c] = __float2half(f[c * NVOX + v]);
    uint4* dst = reinterpret_cast<uint4*>(&g_feat_h[(size_t)v * FD]);
    const uint4* s = reinterpret_cast<const uint4*>(&tmp);
#pragma unroll
    for (int k = 0; k < 4; ++k) dst[k] = s[k];
}

// ---------------------------------------------------------------------------
__device__ __forceinline__ __half2 shfl_xor_h2(__half2 v, int m) {
    unsigned u = *reinterpret_cast<unsigned*>(&v);
    u = __shfl_xor_sync(0xffffffffu, u, m);
    return *reinterpret_cast<__half2*>(&u);
}

// ---------------------------------------------------------------------------
// Quad-cooperative bilinear plane sample.
// Lane k loads 16 B of the 64 B row-pair [texel x0 | texel x0+1].
// After x-exchange: lanes {0,2} hold sampled ch 0-7, lanes {1,3} ch 8-15.
// r[0..3] = 4 half2 = 8 channels.
// ---------------------------------------------------------------------------
__device__ __forceinline__ void sample_plane_rp(const __half* __restrict__ pl,
                                                float a, float b, int k,
                                                __half2 r[4]) {
    float x = fminf(fmaxf((a + 1.0f) * (0.5f * (RESO - 1)), 0.0f), (float)(RESO - 1));
    float y = fminf(fmaxf((b + 1.0f) * (0.5f * (RESO - 1)), 0.0f), (float)(RESO - 1));
    int x0 = min((int)x, RESO - 2);
    int y0 = min((int)y, RESO - 2);
    float fx = x - (float)x0;
    float fy = y - (float)y0;

    // row-pair base: texels (y0, x0) and (y0, x0+1) are contiguous 64 B.
    const uint4* base = reinterpret_cast<const uint4*>(pl + (y0 * RESO + x0) * HPAD) + k;
    constexpr int DY = RESO * 2;   // +1 row, in uint4 units

    uint4 u0 = __ldg(base);        // row y0, lane's 16 B slice
    uint4 u1 = __ldg(base + DY);   // row y0+1

    __half2 wy0 = __float2half2_rn(1.0f - fy);
    __half2 wy1 = __float2half2_rn(fy);

    const __half2* v0 = reinterpret_cast<const __half2*>(&u0);
    const __half2* v1 = reinterpret_cast<const __half2*>(&u1);

    __half2 t[4];
#pragma unroll
    for (int m = 0; m < 4; ++m)
        t[m] = __hfma2(v1[m], wy1, __hmul2(v0[m], wy0));

    // x-blend: partner lane (k^2) holds the other texel's same channel slice.
    bool low = (k & 2) == 0;                   // lanes 0,1 hold x0
    __half2 wa = __float2half2_rn(low ? (1.0f - fx) : fx);
    __half2 wb = __float2half2_rn(low ? fx : (1.0f - fx));
#pragma unroll
    for (int m = 0; m < 4; ++m) {
        __half2 o = shfl_xor_h2(t[m], 2);
        r[m] = __hfma2(o, wb, __hmul2(t[m], wa));
    }
}

// ---------------------------------------------------------------------------
// 4 lanes per point.
// ---------------------------------------------------------------------------
__global__ void __launch_bounds__(256) lrh_main(const float* __restrict__ pts,
                                                float* __restrict__ out, int n) {
    int t = blockIdx.x * blockDim.x + threadIdx.x;
    int i = t >> 2;
    int k = t & 3;
    if (i >= n) return;

    float px = __ldg(pts + 3 * i);
    float py = __ldg(pts + 3 * i + 1);
    float pz = __ldg(pts + 3 * i + 2);

    __half2 s01[4], s02[4], s12[4];
    sample_plane_rp(g_planes_h[0], px, py, k, s01);
    sample_plane_rp(g_planes_h[1], px, pz, k, s02);
    sample_plane_rp(g_planes_h[2], py, pz, k, s12);

    // Triple product (half2), reduce in fp32.
    // lanes {0,2}: ca = coord0 (ch0-3), cb = coord1 (ch4-7)
    // lanes {1,3}: ca = coord2 (ch8-11), cb = pad
    float ca = 0.0f, cb = 0.0f;
#pragma unroll
    for (int m = 0; m < 4; ++m) {
        __half2 h = __hmul2(__hmul2(s01[m], s02[m]), s12[m]);
        float2 f = __half22float2(h);
        if (m < 2) ca += f.x + f.y;
        else       cb += f.x + f.y;
    }

    float cx = __shfl_sync(0xffffffffu, ca, 0, 4);
    float cy = __shfl_sync(0xffffffffu, cb, 0, 4);
    float cz = __shfl_sync(0xffffffffu, ca, 1, 4);

    // Trilinear sample; lane k owns channels 8k..8k+7 (16 B fp16 per corner).
    float x = fminf(fmaxf((cx + 1.0f) * (0.5f * (FR - 1)), 0.0f), (float)(FR - 1));
    float y = fminf(fmaxf((cy + 1.0f) * (0.5f * (FR - 1)), 0.0f), (float)(FR - 1));
    float z = fminf(fmaxf((cz + 1.0f) * (0.5f * (FR - 1)), 0.0f), (float)(FR - 1));
    int x0 = min((int)x, FR - 2);
    int y0 = min((int)y, FR - 2);
    int z0 = min((int)z, FR - 2);
    float fx = x - (float)x0;
    float fy = y - (float)y0;
    float fz = z - (float)z0;

    // voxel = 4 uint4 (64 B); lane k takes uint4 #k.
    const uint4* fb = reinterpret_cast<const uint4*>(g_feat_h)
                    + ((size_t)((z0 * FR + y0) * FR + x0)) * 4 + k;
    constexpr int SX = 4;
    constexpr int SY = FR * 4;
    constexpr int SZ = FR * FR * 4;

    float wx[2] = {1.0f - fx, fx};
    float wy[2] = {1.0f - fy, fy};
    float wz[2] = {1.0f - fz, fz};

    // fp32 accumulators for 8 channels.
    float2 acc[4] = {{0.f,0.f},{0.f,0.f},{0.f,0.f},{0.f,0.f}};

#pragma unroll
    for (int dz = 0; dz < 2; ++dz) {
#pragma unroll
        for (int dy = 0; dy < 2; ++dy) {
#pragma unroll
            for (int dx = 0; dx < 2; ++dx) {
                float w = wz[dz] * wy[dy] * wx[dx];
                uint4 u = __ldg(fb + dz * SZ + dy * SY + dx * SX);
                const __half2* v = reinterpret_cast<const __half2*>(&u);
#pragma unroll
                for (int m = 0; m < 4; ++m) {
                    float2 f = __half22float2(v[m]);
                    acc[m].x = fmaf(w, f.x, acc[m].x);
                    acc[m].y = fmaf(w, f.y, acc[m].y);
                }
            }
        }
    }

    // store channels 8k..8k+7 (32 B); quad covers the full 128 B row.
    float4* op = reinterpret_cast<float4*>(out) + (size_t)i * (FD / 4) + 2 * k;
    op[0] = make_float4(acc[0].x, acc[0].y, acc[1].x, acc[1].y);
    op[1] = make_float4(acc[2].x, acc[2].y, acc[3].x, acc[3].y);
}

// ---------------------------------------------------------------------------
extern "C" void kernel_launch(void* const* d_in, const int* in_sizes, int n_in,
                              void* d_out, int out_size) {
    const float* pts  = (const float*)d_in[0];
    const float* p01  = (const float*)d_in[1];
    const float* p02  = (const float*)d_in[2];
    const float* p12  = (const float*)d_in[3];
    const float* feat = (const float*)d_in[4];
    float* out = (float*)d_out;
    int n = in_sizes[0] / 3;

    prep_planes<<<dim3((RESO * RESO + 255) / 256, 3), 256>>>(p01, p02, p12);
    prep_feat<<<(NVOX + 255) / 256, 256>>>(feat);

    long long threads = 4LL * n;
    lrh_main<<<(int)((threads + 255) / 256), 256>>>(pts, out, n);
}

// round 5
// speedup vs baseline: 2.9020x; 1.0436x over previous
#include <cuda_runtime.h>
#include <cuda_fp16.h>

// ---------------------------------------------------------------------------
// LowrankLearnableHash, round 5: duplicated 2x2-footprint plane grid.
//
//   g_plane_dup: per plane, entry(y0,x0) = all 4 bilinear corner texels,
//     packed as 6 slices of 16 B. Slice p = channel pair p, laid out as
//     4 half2: [c00, c01, c10, c11]. Entry stride 128 B (96 B used) so a
//     plane sample touches exactly ONE cache line / 3 sectors.
//   g_feat_h: [64^3 * 32] fp16 channel-last, 64 B/voxel (unchanged).
//
//   lrh_main: 4 lanes/point. Per plane: lane k LDGs slice k, then slice
//   4+(k&1) (same line -> L1 hit). In-lane bilinear blend (no shuffles).
//   Triple product per channel pair; coords via 2x shfl_xor + 3 shfl.
//   Feature trilinear: lane k owns channels 8k..8k+7, fp32 accumulation.
// ---------------------------------------------------------------------------

namespace {
constexpr int RESO = 256;
constexpr int NTEX = RESO * RESO;
constexpr int ESTRIDE_H = 64;          // entry stride in halfs (128 B)
constexpr int FR   = 64;
constexpr int FD   = 32;
constexpr int NVOX = FR * FR * FR;
}

__device__ __align__(256) __half g_plane_dup[3][NTEX * ESTRIDE_H]; // 24 MB
__device__ __align__(256) __half g_feat_h[NVOX * FD];              // 16 MB

// ---------------------------------------------------------------------------
// Build the duplicated footprint grid. One thread per entry.
// ---------------------------------------------------------------------------
__global__ void prep_dup(const float* __restrict__ p0,
                         const float* __restrict__ p1,
                         const float* __restrict__ p2) {
    int e = blockIdx.x * blockDim.x + threadIdx.x;
    if (e >= NTEX) return;
    int pl = blockIdx.y;
    const float* src = (pl == 0) ? p0 : ((pl == 1) ? p1 : p2);

    int y = e >> 8, x = e & 255;
    int x1 = min(x + 1, RESO - 1);
    int y1 = min(y + 1, RESO - 1);
    int i00 = y  * RESO + x,  i01 = y  * RESO + x1;
    int i10 = y1 * RESO + x,  i11 = y1 * RESO + x1;

    struct alignas(16) Slice { __half2 h[4]; };
    __half* dst = &g_plane_dup[pl][(size_t)e * ESTRIDE_H];

#pragma unroll
    for (int p = 0; p < 6; ++p) {
        const float* c0 = src + (2 * p) * NTEX;
        const float* c1 = src + (2 * p + 1) * NTEX;
        Slice s;
        s.h[0] = __floats2half2_rn(c0[i00], c1[i00]);
        s.h[1] = __floats2half2_rn(c0[i01], c1[i01]);
        s.h[2] = __floats2half2_rn(c0[i10], c1[i10]);
        s.h[3] = __floats2half2_rn(c0[i11], c1[i11]);
        *reinterpret_cast<uint4*>(dst + 8 * p) = *reinterpret_cast<uint4*>(&s);
    }
}

// ---------------------------------------------------------------------------
__global__ void prep_feat(const float* __restrict__ f) {
    int v = blockIdx.x * blockDim.x + threadIdx.x;
    if (v >= NVOX) return;
    struct alignas(32) H32 { __half h[FD]; } tmp;
#pragma unroll
    for (int c = 0; c < FD; ++c) tmp.h[c] = __float2half(f[c * NVOX + v]);
    uint4* dst = reinterpret_cast<uint4*>(&g_feat_h[(size_t)v * FD]);
    const uint4* s = reinterpret_cast<const uint4*>(&tmp);
#pragma unroll
    for (int k = 0; k < 4; ++k) dst[k] = s[k];
}

// ---------------------------------------------------------------------------
// Blend one 16 B slice (4 half2 corners) with bilinear weights.
// ---------------------------------------------------------------------------
__device__ __forceinline__ __half2 blend_slice(uint4 u, __half2 w00, __half2 w01,
                                               __half2 w10, __half2 w11) {
    const __half2* v = reinterpret_cast<const __half2*>(&u);
    __half2 r = __hmul2(v[0], w00);
    r = __hfma2(v[1], w01, r);
    r = __hfma2(v[2], w10, r);
    return __hfma2(v[3], w11, r);
}

// Sample one plane: lane k returns channel-pair k (rA) and pair 4+(k&1) (rB).
__device__ __forceinline__ void sample_plane_dup(const __half* __restrict__ pl,
                                                 float a, float b, int k,
                                                 __half2& rA, __half2& rB) {
    float x = fminf(fmaxf((a + 1.0f) * (0.5f * (RESO - 1)), 0.0f), (float)(RESO - 1));
    float y = fminf(fmaxf((b + 1.0f) * (0.5f * (RESO - 1)), 0.0f), (float)(RESO - 1));
    int x0 = min((int)x, RESO - 2);
    int y0 = min((int)y, RESO - 2);
    float fx = x - (float)x0;
    float fy = y - (float)y0;

    __half2 w00 = __float2half2_rn((1.0f - fx) * (1.0f - fy));
    __half2 w01 = __float2half2_rn(fx * (1.0f - fy));
    __half2 w10 = __float2half2_rn((1.0f - fx) * fy);
    __half2 w11 = __float2half2_rn(fx * fy);

    const uint4* base = reinterpret_cast<const uint4*>(pl) + (size_t)(y0 * RESO + x0) * 8;
    uint4 uA = __ldg(base + k);              // slice k          (pairs 0-3)
    uint4 uB = __ldg(base + 4 + (k & 1));    // slice 4/5 (dim2) -- same line, L1 hit

    rA = blend_slice(uA, w00, w01, w10, w11);
    rB = blend_slice(uB, w00, w01, w10, w11);
}

// ---------------------------------------------------------------------------
// 4 lanes per point.
//   pair p -> channels 2p,2p+1. dim0 = pairs 0,1; dim1 = pairs 2,3;
//   dim2 = pairs 4,5. Lane k owns pair k (A) and pair 4+(k&1) (B).
// ---------------------------------------------------------------------------
__global__ void __launch_bounds__(256) lrh_main(const float* __restrict__ pts,
                                                float* __restrict__ out, int n) {
    int t = blockIdx.x * blockDim.x + threadIdx.x;
    int i = t >> 2;
    int k = t & 3;
    if (i >= n) return;

    float px = __ldg(pts + 3 * i);
    float py = __ldg(pts + 3 * i + 1);
    float pz = __ldg(pts + 3 * i + 2);

    __half2 a01, b01, a02, b02, a12, b12;
    sample_plane_dup(g_plane_dup[0], px, py, k, a01, b01);
    sample_plane_dup(g_plane_dup[1], px, pz, k, a02, b02);
    sample_plane_dup(g_plane_dup[2], py, pz, k, a12, b12);

    __half2 pA = __hmul2(__hmul2(a01, a02), a12);
    __half2 pB = __hmul2(__hmul2(b01, b02), b12);

    float2 fA = __half22float2(pA);
    float2 fB = __half22float2(pB);
    float sA = fA.x + fA.y;      // lane0,1: dim0 halves; lane2,3: dim1 halves
    float sB = fB.x + fB.y;      // lane0,1: dim2 halves; lane2,3: duplicates

    sA += __shfl_xor_sync(0xffffffffu, sA, 1);
    sB += __shfl_xor_sync(0xffffffffu, sB, 1);

    float cx = __shfl_sync(0xffffffffu, sA, 0, 4);
    float cy = __shfl_sync(0xffffffffu, sA, 2, 4);
    float cz = __shfl_sync(0xffffffffu, sB, 0, 4);

    // Trilinear sample; lane k owns channels 8k..8k+7.
    float x = fminf(fmaxf((cx + 1.0f) * (0.5f * (FR - 1)), 0.0f), (float)(FR - 1));
    float y = fminf(fmaxf((cy + 1.0f) * (0.5f * (FR - 1)), 0.0f), (float)(FR - 1));
    float z = fminf(fmaxf((cz + 1.0f) * (0.5f * (FR - 1)), 0.0f), (float)(FR - 1));
    int x0 = min((int)x, FR - 2);
    int y0 = min((int)y, FR - 2);
    int z0 = min((int)z, FR - 2);
    float fx = x - (float)x0;
    float fy = y - (float)y0;
    float fz = z - (float)z0;

    const uint4* fb = reinterpret_cast<const uint4*>(g_feat_h)
                    + ((size_t)((z0 * FR + y0) * FR + x0)) * 4 + k;
    constexpr int SX = 4;
    constexpr int SY = FR * 4;
    constexpr int SZ = FR * FR * 4;

    float wx[2] = {1.0f - fx, fx};
    float wy[2] = {1.0f - fy, fy};
    float wz[2] = {1.0f - fz, fz};

    float2 acc[4] = {{0.f,0.f},{0.f,0.f},{0.f,0.f},{0.f,0.f}};

#pragma unroll
    for (int dz = 0; dz < 2; ++dz) {
#pragma unroll
        for (int dy = 0; dy < 2; ++dy) {
#pragma unroll
            for (int dx = 0; dx < 2; ++dx) {
                float w = wz[dz] * wy[dy] * wx[dx];
                uint4 u = __ldg(fb + dz * SZ + dy * SY + dx * SX);
                const __half2* v = reinterpret_cast<const __half2*>(&u);
#pragma unroll
                for (int m = 0; m < 4; ++m) {
                    float2 f = __half22float2(v[m]);
                    acc[m].x = fmaf(w, f.x, acc[m].x);
                    acc[m].y = fmaf(w, f.y, acc[m].y);
                }
            }
        }
    }

    float4* op = reinterpret_cast<float4*>(out) + (size_t)i * (FD / 4) + 2 * k;
    op[0] = make_float4(acc[0].x, acc[0].y, acc[1].x, acc[1].y);
    op[1] = make_float4(acc[2].x, acc[2].y, acc[3].x, acc[3].y);
}

// ---------------------------------------------------------------------------
extern "C" void kernel_launch(void* const* d_in, const int* in_sizes, int n_in,
                              void* d_out, int out_size) {
    const float* pts  = (const float*)d_in[0];
    const float* p01  = (const float*)d_in[1];
    const float* p02  = (const float*)d_in[2];
    const float* p12  = (const float*)d_in[3];
    const float* feat = (const float*)d_in[4];
    float* out = (float*)d_out;
    int n = in_sizes[0] / 3;

    prep_dup<<<dim3(NTEX / 256, 3), 256>>>(p01, p02, p12);
    prep_feat<<<(NVOX + 255) / 256, 256>>>(feat);

    long long threads = 4LL * n;
    lrh_main<<<(int)((threads + 255) / 256), 256>>>(pts, out, n);
}